// round 1
// baseline (speedup 1.0000x reference)
#include <cuda_runtime.h>
#include <stdint.h>

// Problem constants
#define T_TOK 8192      // B*S tokens
#define H_DIM 2048
#define I_DIM 1408
#define I2    2816      // 2*I
#define E_NUM 8
#define SLOTS 16384     // T_TOK * TOP_K

// ---------------- scratch (device globals; no allocations allowed) ----------
__device__ int8_t g_w13[(size_t)E_NUM * I2 * H_DIM];      // 46.1 MB int8 weights fc1
__device__ int8_t g_w2 [(size_t)E_NUM * H_DIM * I_DIM];   // 23.1 MB int8 weights fc2
__device__ int8_t g_xq [(size_t)T_TOK * H_DIM];           // quantized activations
__device__ float  g_xs [T_TOK];                           // per-token act scale
__device__ int    g_top_e[T_TOK * 2];
__device__ float  g_top_w[T_TOK * 2];
__device__ int    g_counts[E_NUM];
__device__ int    g_off[E_NUM + 1];
__device__ int    g_pos[E_NUM];
__device__ int    g_tok [SLOTS];                          // token id per slot
__device__ float  g_gate[SLOTS];                          // gate weight per slot
__device__ float  g_h  [(size_t)SLOTS * I2];              // fc1 output (fp32), 184.5 MB
__device__ int8_t g_aq [(size_t)SLOTS * I_DIM];           // quantized swiglu output
__device__ float  g_as [SLOTS];                           // per-slot act scale

// ---------------- init: zero routing counters --------------------------------
__global__ void k_init() {
    int i = threadIdx.x;
    if (i < E_NUM) { g_counts[i] = 0; g_pos[i] = 0; }
}

// ---------------- weight int32 -> int8 conversion ----------------------------
__global__ void k_conv13(const int* __restrict__ src) {
    const int n4 = E_NUM * I2 * (H_DIM / 4);
    for (int i = blockIdx.x * blockDim.x + threadIdx.x; i < n4;
         i += gridDim.x * blockDim.x) {
        int4 v = ((const int4*)src)[i];
        char4 c = make_char4((char)v.x, (char)v.y, (char)v.z, (char)v.w);
        ((char4*)g_w13)[i] = c;
    }
}
__global__ void k_conv2(const int* __restrict__ src) {
    const int n4 = E_NUM * H_DIM * (I_DIM / 4);
    for (int i = blockIdx.x * blockDim.x + threadIdx.x; i < n4;
         i += gridDim.x * blockDim.x) {
        int4 v = ((const int4*)src)[i];
        char4 c = make_char4((char)v.x, (char)v.y, (char)v.z, (char)v.w);
        ((char4*)g_w2)[i] = c;
    }
}

// ---------------- gating + dynamic int8 quant (1 block per token) ------------
__global__ void k_gate_quant(const float* __restrict__ x,
                             const float* __restrict__ gw) {
    const int t   = blockIdx.x;
    const int tid = threadIdx.x;   // 256 threads
    __shared__ float sx[H_DIM];
    __shared__ float sred[256];
    __shared__ float slog[E_NUM];
    __shared__ float s_scale;

    const float4* xr = (const float4*)(x + (size_t)t * H_DIM);
    float m = 0.f;
    for (int i = tid; i < H_DIM / 4; i += 256) {
        float4 v = xr[i];
        ((float4*)sx)[i] = v;
        m = fmaxf(m, fmaxf(fmaxf(fabsf(v.x), fabsf(v.y)),
                           fmaxf(fabsf(v.z), fabsf(v.w))));
    }
    sred[tid] = m;
    __syncthreads();
    for (int s = 128; s > 0; s >>= 1) {
        if (tid < s) sred[tid] = fmaxf(sred[tid], sred[tid + s]);
        __syncthreads();
    }
    if (tid == 0) s_scale = fmaxf(sred[0] / 127.f, 1e-8f);
    __syncthreads();
    const float scale = s_scale;

    // logits: 8 experts at once per element pass
    float lacc[E_NUM];
#pragma unroll
    for (int e = 0; e < E_NUM; e++) lacc[e] = 0.f;
    for (int i = tid; i < H_DIM / 4; i += 256) {
        float4 v = ((float4*)sx)[i];
#pragma unroll
        for (int e = 0; e < E_NUM; e++) {
            float4 w = ((const float4*)(gw + (size_t)e * H_DIM))[i];
            lacc[e] += v.x * w.x + v.y * w.y + v.z * w.z + v.w * w.w;
        }
    }
#pragma unroll
    for (int e = 0; e < E_NUM; e++) {
        sred[tid] = lacc[e];
        __syncthreads();
        for (int s = 128; s > 0; s >>= 1) {
            if (tid < s) sred[tid] += sred[tid + s];
            __syncthreads();
        }
        if (tid == 0) slog[e] = sred[0];
        __syncthreads();
    }

    // quantize activations: q = clip(rint(x / s), -127, 127)
    for (int i = tid; i < H_DIM / 4; i += 256) {
        float4 v = ((float4*)sx)[i];
        char4 q;
        q.x = (char)(int)fminf(fmaxf(rintf(v.x / scale), -127.f), 127.f);
        q.y = (char)(int)fminf(fmaxf(rintf(v.y / scale), -127.f), 127.f);
        q.z = (char)(int)fminf(fmaxf(rintf(v.z / scale), -127.f), 127.f);
        q.w = (char)(int)fminf(fmaxf(rintf(v.w / scale), -127.f), 127.f);
        ((char4*)(g_xq + (size_t)t * H_DIM))[i] = q;
    }

    if (tid == 0) {
        g_xs[t] = scale;
        // softmax over 8 + top2 (stable, lowest index on tie, like lax.top_k)
        float mx = slog[0];
#pragma unroll
        for (int e = 1; e < E_NUM; e++) mx = fmaxf(mx, slog[e]);
        float p[E_NUM];
        float se = 0.f;
#pragma unroll
        for (int e = 0; e < E_NUM; e++) { p[e] = expf(slog[e] - mx); se += p[e]; }
#pragma unroll
        for (int e = 0; e < E_NUM; e++) p[e] /= se;
        int i0 = 0;
#pragma unroll
        for (int e = 1; e < E_NUM; e++) if (p[e] > p[i0]) i0 = e;
        int i1 = (i0 == 0) ? 1 : 0;
#pragma unroll
        for (int e = 0; e < E_NUM; e++)
            if (e != i0 && p[e] > p[i1]) i1 = e;
        float ws = p[i0] + p[i1];
        g_top_e[2 * t]     = i0;
        g_top_e[2 * t + 1] = i1;
        g_top_w[2 * t]     = p[i0] / ws;
        g_top_w[2 * t + 1] = p[i1] / ws;
        atomicAdd(&g_counts[i0], 1);
        atomicAdd(&g_counts[i1], 1);
    }
}

// ---------------- routing scan + scatter -------------------------------------
__global__ void k_scan() {
    if (threadIdx.x == 0) {
        int o = 0;
        for (int e = 0; e < E_NUM; e++) {
            g_off[e] = o; g_pos[e] = o; o += g_counts[e];
        }
        g_off[E_NUM] = o;
    }
}
__global__ void k_scatter() {
    int t = blockIdx.x * blockDim.x + threadIdx.x;
    if (t >= T_TOK) return;
#pragma unroll
    for (int k = 0; k < 2; k++) {
        int e = g_top_e[2 * t + k];
        int slot = atomicAdd(&g_pos[e], 1);
        g_tok[slot]  = t;
        g_gate[slot] = g_top_w[2 * t + k];
    }
}

// ---------------- fc1 grouped int8 GEMM: [rows_e,2048] x [2816,2048]^T -------
// BM=64, BN=64, BK=64 bytes (16 packed ints), 256 threads, 4x4 per thread.
__global__ void k_fc1(const float* __restrict__ s13) {
    const int e  = blockIdx.z;
    const int mt = blockIdx.y;
    const int nt = blockIdx.x;
    const int base = g_off[e];
    const int rows = g_off[e + 1] - base;
    const int row0 = mt * 64;
    if (row0 >= rows) return;

    __shared__ int As[64][17];
    __shared__ int Bs[64][17];
    __shared__ int s_tok[64];

    const int tid = threadIdx.x;
    const int tx = tid & 15, ty = tid >> 4;

    if (tid < 64) {
        int r = row0 + tid;
        s_tok[tid] = (r < rows) ? g_tok[base + r] : -1;
    }
    __syncthreads();

    int acc[4][4] = {};
    const int* w13i = (const int*)g_w13;
    const size_t wbase = ((size_t)e * I2 + (size_t)nt * 64) * (H_DIM / 4);
    const int* xqi = (const int*)g_xq;

    for (int kt = 0; kt < H_DIM / 64; kt++) {
#pragma unroll
        for (int q = 0; q < 4; q++) {
            int lin = q * 256 + tid;
            int r = lin >> 4, kk = lin & 15;
            int tok = s_tok[r];
            As[r][kk] = (tok >= 0)
                ? xqi[(size_t)tok * (H_DIM / 4) + kt * 16 + kk] : 0;
            Bs[r][kk] = w13i[wbase + (size_t)r * (H_DIM / 4) + kt * 16 + kk];
        }
        __syncthreads();
#pragma unroll
        for (int kk = 0; kk < 16; kk++) {
            int a[4], b[4];
#pragma unroll
            for (int i = 0; i < 4; i++) a[i] = As[ty * 4 + i][kk];
#pragma unroll
            for (int j = 0; j < 4; j++) b[j] = Bs[tx + 16 * j][kk];
#pragma unroll
            for (int i = 0; i < 4; i++)
#pragma unroll
                for (int j = 0; j < 4; j++)
                    acc[i][j] = __dp4a(a[i], b[j], acc[i][j]);
        }
        __syncthreads();
    }

#pragma unroll
    for (int i = 0; i < 4; i++) {
        int r = row0 + ty * 4 + i;
        if (r < rows) {
            int tok = s_tok[ty * 4 + i];
            float xs = g_xs[tok];
            float* hrow = &g_h[(size_t)(base + r) * I2];
#pragma unroll
            for (int j = 0; j < 4; j++) {
                int col = nt * 64 + 16 * j + tx;
                hrow[col] = (float)acc[i][j] * xs * __ldg(&s13[e * I2 + col]);
            }
        }
    }
}

// ---------------- SwiGLU + dynamic int8 requant (1 block per slot) -----------
__global__ void k_swiglu() {
    const int slot = blockIdx.x;
    const int tid = threadIdx.x;  // 256
    __shared__ float sa[I_DIM];
    __shared__ float sred[256];
    __shared__ float s_scale;

    const float* h = &g_h[(size_t)slot * I2];
    float m = 0.f;
    for (int i = tid; i < I_DIM; i += 256) {
        float g = h[i];
        float u = h[I_DIM + i];
        float a = (g / (1.f + expf(-g))) * u;   // silu(g) * u
        sa[i] = a;
        m = fmaxf(m, fabsf(a));
    }
    sred[tid] = m;
    __syncthreads();
    for (int s = 128; s > 0; s >>= 1) {
        if (tid < s) sred[tid] = fmaxf(sred[tid], sred[tid + s]);
        __syncthreads();
    }
    if (tid == 0) { s_scale = fmaxf(sred[0] / 127.f, 1e-8f); g_as[slot] = s_scale; }
    __syncthreads();
    const float scale = s_scale;
    for (int i = tid; i < I_DIM / 4; i += 256) {
        float4 v = ((float4*)sa)[i];
        char4 q;
        q.x = (char)(int)fminf(fmaxf(rintf(v.x / scale), -127.f), 127.f);
        q.y = (char)(int)fminf(fmaxf(rintf(v.y / scale), -127.f), 127.f);
        q.z = (char)(int)fminf(fmaxf(rintf(v.z / scale), -127.f), 127.f);
        q.w = (char)(int)fminf(fmaxf(rintf(v.w / scale), -127.f), 127.f);
        ((char4*)(g_aq + (size_t)slot * I_DIM))[i] = q;
    }
}

// ---------------- init output with shared_output -----------------------------
__global__ void k_copy(float* __restrict__ out, const float* __restrict__ sh) {
    const int n4 = T_TOK * (H_DIM / 4);
    for (int i = blockIdx.x * blockDim.x + threadIdx.x; i < n4;
         i += gridDim.x * blockDim.x)
        ((float4*)out)[i] = ((const float4*)sh)[i];
}

// ---------------- fc2 grouped int8 GEMM + weighted combine -------------------
__global__ void k_fc2(const float* __restrict__ s2, float* __restrict__ out) {
    const int e  = blockIdx.z;
    const int mt = blockIdx.y;
    const int nt = blockIdx.x;
    const int base = g_off[e];
    const int rows = g_off[e + 1] - base;
    const int row0 = mt * 64;
    if (row0 >= rows) return;

    __shared__ int As[64][17];
    __shared__ int Bs[64][17];

    const int tid = threadIdx.x;
    const int tx = tid & 15, ty = tid >> 4;

    int acc[4][4] = {};
    const int* w2i = (const int*)g_w2;
    const size_t wbase = ((size_t)e * H_DIM + (size_t)nt * 64) * (I_DIM / 4);
    const int* aqi = (const int*)g_aq;

    for (int kt = 0; kt < I_DIM / 64; kt++) {
#pragma unroll
        for (int q = 0; q < 4; q++) {
            int lin = q * 256 + tid;
            int r = lin >> 4, kk = lin & 15;
            int gr = row0 + r;
            As[r][kk] = (gr < rows)
                ? aqi[(size_t)(base + gr) * (I_DIM / 4) + kt * 16 + kk] : 0;
            Bs[r][kk] = w2i[wbase + (size_t)r * (I_DIM / 4) + kt * 16 + kk];
        }
        __syncthreads();
#pragma unroll
        for (int kk = 0; kk < 16; kk++) {
            int a[4], b[4];
#pragma unroll
            for (int i = 0; i < 4; i++) a[i] = As[ty * 4 + i][kk];
#pragma unroll
            for (int j = 0; j < 4; j++) b[j] = Bs[tx + 16 * j][kk];
#pragma unroll
            for (int i = 0; i < 4; i++)
#pragma unroll
                for (int j = 0; j < 4; j++)
                    acc[i][j] = __dp4a(a[i], b[j], acc[i][j]);
        }
        __syncthreads();
    }

#pragma unroll
    for (int i = 0; i < 4; i++) {
        int r = row0 + ty * 4 + i;
        if (r < rows) {
            int slot = base + r;
            int tok = g_tok[slot];
            float f = g_as[slot] * g_gate[slot];  // ROUTED_SCALING = 1
#pragma unroll
            for (int j = 0; j < 4; j++) {
                int col = nt * 64 + 16 * j + tx;
                atomicAdd(&out[(size_t)tok * H_DIM + col],
                          (float)acc[i][j] * f * __ldg(&s2[e * H_DIM + col]));
            }
        }
    }
}

// ---------------- launch ------------------------------------------------------
extern "C" void kernel_launch(void* const* d_in, const int* in_sizes, int n_in,
                              void* d_out, int out_size) {
    const float* x    = (const float*)d_in[0];  // hidden_states [T,H]
    const float* gw   = (const float*)d_in[1];  // gate_w [E,H]
    const int*   w13q = (const int*)  d_in[2];  // [E,2I,H] int32
    const float* s13  = (const float*)d_in[3];  // [E,2I]
    const int*   w2q  = (const int*)  d_in[4];  // [E,H,I] int32
    const float* s2   = (const float*)d_in[5];  // [E,H]
    const float* sh   = (const float*)d_in[6];  // shared_output [T,H]
    float* out = (float*)d_out;

    k_init<<<1, 32>>>();
    k_conv13<<<4096, 256>>>(w13q);
    k_conv2<<<4096, 256>>>(w2q);
    k_gate_quant<<<T_TOK, 256>>>(x, gw);
    k_scan<<<1, 32>>>();
    k_scatter<<<T_TOK / 256, 256>>>();
    k_fc1<<<dim3(I2 / 64, T_TOK / 64, E_NUM), 256>>>(s13);
    k_swiglu<<<SLOTS, 256>>>();
    k_copy<<<4096, 256>>>(out, sh);
    k_fc2<<<dim3(H_DIM / 64, T_TOK / 64, E_NUM), 256>>>(s2, out);
}

// round 3
// speedup vs baseline: 1.2779x; 1.2779x over previous
#include <cuda_runtime.h>
#include <stdint.h>

// Problem constants
#define T_TOK 8192
#define H_DIM 2048
#define I_DIM 1408
#define I2    2816
#define E_NUM 8
#define SLOTS 16384

// ---------------- scratch ----------------------------------------------------
__device__ int8_t g_w13[(size_t)E_NUM * I2 * H_DIM];
__device__ int8_t g_w2 [(size_t)E_NUM * H_DIM * I_DIM];
__device__ int8_t g_xq [(size_t)T_TOK * H_DIM];
__device__ float  g_xs [T_TOK];
__device__ int    g_top_e[T_TOK * 2];
__device__ float  g_top_w[T_TOK * 2];
__device__ int    g_counts[E_NUM];
__device__ int    g_off[E_NUM + 1];
__device__ int    g_pos[E_NUM];
__device__ int    g_tok [SLOTS];
__device__ float  g_gate[SLOTS];
__device__ int    g_slot_of[T_TOK * 2];
__device__ float  g_h  [(size_t)SLOTS * I2];      // fc1 out fp32
__device__ int8_t g_aq [(size_t)SLOTS * I_DIM];
__device__ float  g_as [SLOTS];
__device__ float  g_y  [(size_t)SLOTS * H_DIM];   // fc2 per-slot out fp32

// ---------------- helpers ----------------------------------------------------
__device__ __forceinline__ uint32_t smem_u32(const void* p) {
    uint32_t a;
    asm("{ .reg .u64 t; cvta.to.shared.u64 t, %1; cvt.u32.u64 %0, t; }"
        : "=r"(a) : "l"(p));
    return a;
}
#define CP16(dst, src, sz) \
    asm volatile("cp.async.ca.shared.global [%0], [%1], 16, %2;" \
                 :: "r"(dst), "l"(src), "r"(sz) : "memory")
#define CP_COMMIT() asm volatile("cp.async.commit_group;" ::: "memory")
#define CP_WAIT1()  asm volatile("cp.async.wait_group 1;" ::: "memory")
#define CP_WAIT0()  asm volatile("cp.async.wait_group 0;" ::: "memory")

__device__ __forceinline__ void ldm_x4(uint32_t* r, uint32_t addr) {
    asm volatile("ldmatrix.sync.aligned.m8n8.x4.shared.b16 {%0,%1,%2,%3}, [%4];"
                 : "=r"(r[0]), "=r"(r[1]), "=r"(r[2]), "=r"(r[3]) : "r"(addr));
}
__device__ __forceinline__ void mma_s8(int* c, const uint32_t* a,
                                       uint32_t b0, uint32_t b1) {
    asm volatile(
        "mma.sync.aligned.m16n8k32.row.col.s32.s8.s8.s32 "
        "{%0,%1,%2,%3}, {%4,%5,%6,%7}, {%8,%9}, {%0,%1,%2,%3};"
        : "+r"(c[0]), "+r"(c[1]), "+r"(c[2]), "+r"(c[3])
        : "r"(a[0]), "r"(a[1]), "r"(a[2]), "r"(a[3]), "r"(b0), "r"(b1));
}

// SMEM tile: 128 rows x 64B(K), padded stride 80B (conflict-free ldmatrix)
#define TROW 80
#define TBYTES (128 * TROW)

// ---------------- init -------------------------------------------------------
__global__ void k_init() {
    int i = threadIdx.x;
    if (i < E_NUM) { g_counts[i] = 0; g_pos[i] = 0; }
}

// ---------------- weight int32 -> int8 ---------------------------------------
__global__ void k_conv13(const int* __restrict__ src) {
    const int n4 = E_NUM * I2 * (H_DIM / 4);
    for (int i = blockIdx.x * blockDim.x + threadIdx.x; i < n4;
         i += gridDim.x * blockDim.x) {
        int4 v = ((const int4*)src)[i];
        ((char4*)g_w13)[i] = make_char4((char)v.x, (char)v.y, (char)v.z, (char)v.w);
    }
}
__global__ void k_conv2(const int* __restrict__ src) {
    const int n4 = E_NUM * H_DIM * (I_DIM / 4);
    for (int i = blockIdx.x * blockDim.x + threadIdx.x; i < n4;
         i += gridDim.x * blockDim.x) {
        int4 v = ((const int4*)src)[i];
        ((char4*)g_w2)[i] = make_char4((char)v.x, (char)v.y, (char)v.z, (char)v.w);
    }
}

// ---------------- gating + dynamic int8 quant --------------------------------
__global__ void k_gate_quant(const float* __restrict__ x,
                             const float* __restrict__ gw) {
    const int t   = blockIdx.x;
    const int tid = threadIdx.x;  // 256
    __shared__ float sx[H_DIM];
    __shared__ float sred[256];
    __shared__ float slog[E_NUM];
    __shared__ float s_scale;

    const float4* xr = (const float4*)(x + (size_t)t * H_DIM);
    float m = 0.f;
    for (int i = tid; i < H_DIM / 4; i += 256) {
        float4 v = xr[i];
        ((float4*)sx)[i] = v;
        m = fmaxf(m, fmaxf(fmaxf(fabsf(v.x), fabsf(v.y)),
                           fmaxf(fabsf(v.z), fabsf(v.w))));
    }
    sred[tid] = m;
    __syncthreads();
    for (int s = 128; s > 0; s >>= 1) {
        if (tid < s) sred[tid] = fmaxf(sred[tid], sred[tid + s]);
        __syncthreads();
    }
    if (tid == 0) s_scale = fmaxf(sred[0] / 127.f, 1e-8f);
    __syncthreads();
    const float scale = s_scale;

    float lacc[E_NUM];
#pragma unroll
    for (int e = 0; e < E_NUM; e++) lacc[e] = 0.f;
    for (int i = tid; i < H_DIM / 4; i += 256) {
        float4 v = ((float4*)sx)[i];
#pragma unroll
        for (int e = 0; e < E_NUM; e++) {
            float4 w = ((const float4*)(gw + (size_t)e * H_DIM))[i];
            lacc[e] += v.x * w.x + v.y * w.y + v.z * w.z + v.w * w.w;
        }
    }
#pragma unroll
    for (int e = 0; e < E_NUM; e++) {
        sred[tid] = lacc[e];
        __syncthreads();
        for (int s = 128; s > 0; s >>= 1) {
            if (tid < s) sred[tid] += sred[tid + s];
            __syncthreads();
        }
        if (tid == 0) slog[e] = sred[0];
        __syncthreads();
    }

    for (int i = tid; i < H_DIM / 4; i += 256) {
        float4 v = ((float4*)sx)[i];
        char4 q;
        q.x = (char)(int)fminf(fmaxf(rintf(v.x / scale), -127.f), 127.f);
        q.y = (char)(int)fminf(fmaxf(rintf(v.y / scale), -127.f), 127.f);
        q.z = (char)(int)fminf(fmaxf(rintf(v.z / scale), -127.f), 127.f);
        q.w = (char)(int)fminf(fmaxf(rintf(v.w / scale), -127.f), 127.f);
        ((char4*)(g_xq + (size_t)t * H_DIM))[i] = q;
    }

    if (tid == 0) {
        g_xs[t] = scale;
        float mx = slog[0];
#pragma unroll
        for (int e = 1; e < E_NUM; e++) mx = fmaxf(mx, slog[e]);
        float p[E_NUM], se = 0.f;
#pragma unroll
        for (int e = 0; e < E_NUM; e++) { p[e] = expf(slog[e] - mx); se += p[e]; }
#pragma unroll
        for (int e = 0; e < E_NUM; e++) p[e] /= se;
        int i0 = 0;
#pragma unroll
        for (int e = 1; e < E_NUM; e++) if (p[e] > p[i0]) i0 = e;
        int i1 = (i0 == 0) ? 1 : 0;
#pragma unroll
        for (int e = 0; e < E_NUM; e++)
            if (e != i0 && p[e] > p[i1]) i1 = e;
        float ws = p[i0] + p[i1];
        g_top_e[2 * t]     = i0;
        g_top_e[2 * t + 1] = i1;
        g_top_w[2 * t]     = p[i0] / ws;
        g_top_w[2 * t + 1] = p[i1] / ws;
        atomicAdd(&g_counts[i0], 1);
        atomicAdd(&g_counts[i1], 1);
    }
}

// ---------------- routing ----------------------------------------------------
__global__ void k_scan() {
    if (threadIdx.x == 0) {
        int o = 0;
        for (int e = 0; e < E_NUM; e++) { g_off[e] = o; g_pos[e] = o; o += g_counts[e]; }
        g_off[E_NUM] = o;
    }
}
__global__ void k_scatter() {
    int t = blockIdx.x * blockDim.x + threadIdx.x;
    if (t >= T_TOK) return;
#pragma unroll
    for (int k = 0; k < 2; k++) {
        int e = g_top_e[2 * t + k];
        int slot = atomicAdd(&g_pos[e], 1);
        g_tok[slot]  = t;
        g_gate[slot] = g_top_w[2 * t + k];
        g_slot_of[2 * t + k] = slot;
    }
}

// ================= IMMA grouped GEMM core (shared by fc1/fc2) ================
// 256 threads; tile M=128 x N=128, BK=64; warp grid 4(M) x 2(N);
// warp tile 32(M) x 64(N): 2 m-frags x 8 n-frags of m16n8k32.
struct GemmOut {
    int c[2][8][4];
    int m0, n0;  // warp tile origin inside CTA tile
};

template <int NK>
__device__ __forceinline__ void gemm_core(
    int8_t* sA, int8_t* sB,                  // [2][TBYTES] each
    const int8_t* arow, int apred,           // per-thread A src row (+32B lane off), 16|0
    const int8_t* brow,                      // per-thread B src row
    uint32_t aoff,                           // this thread's smem store offset
    GemmOut& out)
{
    const int tid  = threadIdx.x;
    const int wid  = tid >> 5, lane = tid & 31;
    const int m0   = (wid & 3) * 32;
    const int n0   = (wid >> 2) * 64;
    out.m0 = m0; out.n0 = n0;
#pragma unroll
    for (int im = 0; im < 2; im++)
#pragma unroll
        for (int jn = 0; jn < 8; jn++)
#pragma unroll
            for (int q = 0; q < 4; q++) out.c[im][jn][q] = 0;

    const uint32_t sAa = smem_u32(sA);
    const uint32_t sBa = smem_u32(sB);
    // ldmatrix lane-address components
    const uint32_t a_lrow = (uint32_t)(lane & 15) * TROW + ((lane >> 4) << 4);
    const uint32_t b_lrow = (uint32_t)(((lane >> 4) << 3) + (lane & 7)) * TROW
                          + (((lane >> 3) & 1) << 4);

    // prefetch kt=0,1
#pragma unroll
    for (int p = 0; p < 2; p++) {
        uint32_t ad = sAa + p * TBYTES + aoff;
        uint32_t bd = sBa + p * TBYTES + aoff;
        CP16(ad,      arow + p * 64,      apred);
        CP16(ad + 16, arow + p * 64 + 16, apred);
        CP16(bd,      brow + p * 64,      16);
        CP16(bd + 16, brow + p * 64 + 16, 16);
        CP_COMMIT();
    }

    for (int kt = 0; kt < NK; kt++) {
        const int buf = kt & 1;
        if (kt + 1 < NK) CP_WAIT1(); else CP_WAIT0();
        __syncthreads();

        const uint32_t Ab = sAa + buf * TBYTES;
        const uint32_t Bb = sBa + buf * TBYTES;
#pragma unroll
        for (int ks = 0; ks < 2; ks++) {
            uint32_t afr[2][4], bfr[4][4];
#pragma unroll
            for (int im = 0; im < 2; im++)
                ldm_x4(afr[im], Ab + (uint32_t)(m0 + im * 16) * TROW + ks * 32 + a_lrow);
#pragma unroll
            for (int in_ = 0; in_ < 4; in_++)
                ldm_x4(bfr[in_], Bb + (uint32_t)(n0 + in_ * 16) * TROW + ks * 32 + b_lrow);
#pragma unroll
            for (int im = 0; im < 2; im++)
#pragma unroll
                for (int jn = 0; jn < 8; jn++) {
                    uint32_t b0 = bfr[jn >> 1][(jn & 1) * 2];
                    uint32_t b1 = bfr[jn >> 1][(jn & 1) * 2 + 1];
                    mma_s8(out.c[im][jn], afr[im], b0, b1);
                }
        }
        __syncthreads();
        if (kt + 2 < NK) {
            uint32_t ad = sAa + buf * TBYTES + aoff;
            uint32_t bd = sBa + buf * TBYTES + aoff;
            CP16(ad,      arow + (kt + 2) * 64,      apred);
            CP16(ad + 16, arow + (kt + 2) * 64 + 16, apred);
            CP16(bd,      brow + (kt + 2) * 64,      16);
            CP16(bd + 16, brow + (kt + 2) * 64 + 16, 16);
        }
        CP_COMMIT();
    }
}

// ---------------- fc1: [rows_e,2048] x w13[e]^T -> g_h -----------------------
__global__ void __launch_bounds__(256) k_fc1(const float* __restrict__ s13) {
    const int e  = blockIdx.z;
    const int mt = blockIdx.y;
    const int nt = blockIdx.x;
    const int base = g_off[e];
    const int rows = g_off[e + 1] - base;
    const int row0 = mt * 128;
    if (row0 >= rows) return;

    __shared__ int8_t sA[2 * TBYTES];
    __shared__ int8_t sB[2 * TBYTES];
    __shared__ int s_tok[128];

    const int tid = threadIdx.x;
    if (tid < 128) {
        int r = row0 + tid;
        s_tok[tid] = (r < rows) ? g_tok[base + r] : -1;
    }
    __syncthreads();

    const int lrow = tid >> 1;
    const int lc   = (tid & 1) * 32;
    const int ltok = s_tok[lrow];
    const int8_t* arow = (ltok >= 0) ? g_xq + (size_t)ltok * H_DIM + lc : g_xq;
    const int apred = (ltok >= 0) ? 16 : 0;
    const int8_t* brow = g_w13 + ((size_t)e * I2 + (size_t)nt * 128 + lrow) * H_DIM + lc;
    const uint32_t aoff = (uint32_t)lrow * TROW + lc;

    GemmOut o;
    gemm_core<H_DIM / 64>(sA, sB, arow, apred, brow, aoff, o);

    // epilogue
    const int lane = tid & 31;
    const int tr = lane >> 2, tc2 = (lane & 3) * 2;
#pragma unroll
    for (int im = 0; im < 2; im++) {
        const int lr0 = o.m0 + im * 16 + tr;
        const int lr1 = lr0 + 8;
        const int gr0 = row0 + lr0, gr1 = row0 + lr1;
        const bool v0 = gr0 < rows, v1 = gr1 < rows;
        const float xs0 = v0 ? g_xs[s_tok[lr0]] : 0.f;
        const float xs1 = v1 ? g_xs[s_tok[lr1]] : 0.f;
        float* h0 = g_h + (size_t)(base + gr0) * I2;
        float* h1 = g_h + (size_t)(base + gr1) * I2;
#pragma unroll
        for (int jn = 0; jn < 8; jn++) {
            int col = nt * 128 + o.n0 + jn * 8 + tc2;
            float2 sc = *(const float2*)&s13[e * I2 + col];
            if (v0) {
                float2 w = { (float)o.c[im][jn][0] * xs0 * sc.x,
                             (float)o.c[im][jn][1] * xs0 * sc.y };
                *(float2*)&h0[col] = w;
            }
            if (v1) {
                float2 w = { (float)o.c[im][jn][2] * xs1 * sc.x,
                             (float)o.c[im][jn][3] * xs1 * sc.y };
                *(float2*)&h1[col] = w;
            }
        }
    }
}

// ---------------- SwiGLU + requant -------------------------------------------
__global__ void k_swiglu() {
    const int slot = blockIdx.x;
    const int tid = threadIdx.x;  // 256
    __shared__ float sa[I_DIM];
    __shared__ float sred[256];
    __shared__ float s_scale;

    const float* h = &g_h[(size_t)slot * I2];
    float m = 0.f;
    for (int i = tid; i < I_DIM; i += 256) {
        float g = h[i];
        float u = h[I_DIM + i];
        float a = (g / (1.f + expf(-g))) * u;
        sa[i] = a;
        m = fmaxf(m, fabsf(a));
    }
    sred[tid] = m;
    __syncthreads();
    for (int s = 128; s > 0; s >>= 1) {
        if (tid < s) sred[tid] = fmaxf(sred[tid], sred[tid + s]);
        __syncthreads();
    }
    if (tid == 0) { s_scale = fmaxf(sred[0] / 127.f, 1e-8f); g_as[slot] = s_scale; }
    __syncthreads();
    const float scale = s_scale;
    for (int i = tid; i < I_DIM / 4; i += 256) {
        float4 v = ((float4*)sa)[i];
        char4 q;
        q.x = (char)(int)fminf(fmaxf(rintf(v.x / scale), -127.f), 127.f);
        q.y = (char)(int)fminf(fmaxf(rintf(v.y / scale), -127.f), 127.f);
        q.z = (char)(int)fminf(fmaxf(rintf(v.z / scale), -127.f), 127.f);
        q.w = (char)(int)fminf(fmaxf(rintf(v.w / scale), -127.f), 127.f);
        ((char4*)(g_aq + (size_t)slot * I_DIM))[i] = q;
    }
}

// ---------------- fc2: [rows_e,1408] x w2[e]^T -> g_y ------------------------
__global__ void __launch_bounds__(256) k_fc2(const float* __restrict__ s2) {
    const int e  = blockIdx.z;
    const int mt = blockIdx.y;
    const int nt = blockIdx.x;
    const int base = g_off[e];
    const int rows = g_off[e + 1] - base;
    const int row0 = mt * 128;
    if (row0 >= rows) return;

    __shared__ int8_t sA[2 * TBYTES];
    __shared__ int8_t sB[2 * TBYTES];

    const int tid = threadIdx.x;
    const int lrow = tid >> 1;
    const int lc   = (tid & 1) * 32;
    const int grl  = row0 + lrow;
    const bool vl  = grl < rows;
    const int8_t* arow = vl ? g_aq + (size_t)(base + grl) * I_DIM + lc : g_aq;
    const int apred = vl ? 16 : 0;
    const int8_t* brow = g_w2 + ((size_t)e * H_DIM + (size_t)nt * 128 + lrow) * I_DIM + lc;
    const uint32_t aoff = (uint32_t)lrow * TROW + lc;

    GemmOut o;
    gemm_core<I_DIM / 64>(sA, sB, arow, apred, brow, aoff, o);

    const int lane = tid & 31;
    const int tr = lane >> 2, tc2 = (lane & 3) * 2;
#pragma unroll
    for (int im = 0; im < 2; im++) {
        const int gr0 = row0 + o.m0 + im * 16 + tr;
        const int gr1 = gr0 + 8;
        const bool v0 = gr0 < rows, v1 = gr1 < rows;
        const int sl0 = base + gr0, sl1 = base + gr1;
        const float f0 = v0 ? g_as[sl0] * g_gate[sl0] : 0.f;
        const float f1 = v1 ? g_as[sl1] * g_gate[sl1] : 0.f;
        float* y0 = g_y + (size_t)sl0 * H_DIM;
        float* y1 = g_y + (size_t)sl1 * H_DIM;
#pragma unroll
        for (int jn = 0; jn < 8; jn++) {
            int col = nt * 128 + o.n0 + jn * 8 + tc2;
            float2 sc = *(const float2*)&s2[e * H_DIM + col];
            if (v0) {
                float2 w = { (float)o.c[im][jn][0] * f0 * sc.x,
                             (float)o.c[im][jn][1] * f0 * sc.y };
                *(float2*)&y0[col] = w;
            }
            if (v1) {
                float2 w = { (float)o.c[im][jn][2] * f1 * sc.x,
                             (float)o.c[im][jn][3] * f1 * sc.y };
                *(float2*)&y1[col] = w;
            }
        }
    }
}

// ---------------- combine ----------------------------------------------------
__global__ void k_combine(float* __restrict__ out, const float* __restrict__ sh) {
    int idx = blockIdx.x * blockDim.x + threadIdx.x;
    const int n4 = T_TOK * (H_DIM / 4);
    if (idx >= n4) return;
    int t = idx / (H_DIM / 4);
    int i = idx % (H_DIM / 4);
    int s0 = g_slot_of[2 * t];
    int s1 = g_slot_of[2 * t + 1];
    float4 a  = ((const float4*)sh)[idx];
    float4 y0 = ((const float4*)(g_y + (size_t)s0 * H_DIM))[i];
    float4 y1 = ((const float4*)(g_y + (size_t)s1 * H_DIM))[i];
    float4 o;
    o.x = a.x + y0.x + y1.x;
    o.y = a.y + y0.y + y1.y;
    o.z = a.z + y0.z + y1.z;
    o.w = a.w + y0.w + y1.w;
    ((float4*)out)[idx] = o;
}

// ---------------- launch ------------------------------------------------------
extern "C" void kernel_launch(void* const* d_in, const int* in_sizes, int n_in,
                              void* d_out, int out_size) {
    const float* x    = (const float*)d_in[0];
    const float* gw   = (const float*)d_in[1];
    const int*   w13q = (const int*)  d_in[2];
    const float* s13  = (const float*)d_in[3];
    const int*   w2q  = (const int*)  d_in[4];
    const float* s2   = (const float*)d_in[5];
    const float* sh   = (const float*)d_in[6];
    float* out = (float*)d_out;

    k_init<<<1, 32>>>();
    k_conv13<<<4096, 256>>>(w13q);
    k_conv2<<<4096, 256>>>(w2q);
    k_gate_quant<<<T_TOK, 256>>>(x, gw);
    k_scan<<<1, 32>>>();
    k_scatter<<<T_TOK / 256, 256>>>();
    k_fc1<<<dim3(I2 / 128, T_TOK / 128, E_NUM), 256>>>(s13);
    k_swiglu<<<SLOTS, 256>>>();
    k_fc2<<<dim3(H_DIM / 128, T_TOK / 128, E_NUM), 256>>>(s2);
    k_combine<<<(T_TOK * (H_DIM / 4) + 255) / 256, 256>>>(out, sh);
}